// round 5
// baseline (speedup 1.0000x reference)
#include <cuda_runtime.h>
#include <math_constants.h>

#define NI 16384          // inputs per batch row
#define ND 65536          // detectors
#define KK 32             // members per detector (== warp size)
#define BB 32             // batch
#define NCHUNK 16         // detector chunks
#define DET_PER_CTA (ND / NCHUNK)   // 4096
#define THREADS 1024
#define WARPS (THREADS / 32)        // 32
#define DET_PER_WARP (DET_PER_CTA / WARPS)  // 128
#define SMEM_BYTES (NI * 8)         // fused (value, flag) per input = 128KB

__global__ void init_out_kernel(float4* __restrict__ out) {
    int i = blockIdx.x * blockDim.x + threadIdx.x;   // covers BB*NI/4
    out[i] = make_float4(1.0f, 1.0f, 1.0f, 1.0f);
}

// Order-preserving float -> unsigned key: x >= y (as floats) iff
// key(x) >= key(y) as unsigned. Equal floats -> equal keys.
__device__ __forceinline__ unsigned f32_order_key(unsigned u) {
    return u ^ (((int)u >> 31) | 0x80000000u);
}

__global__ void __launch_bounds__(THREADS, 1) inhibit_kernel(
    const float* __restrict__ x,
    const int*   __restrict__ det,
    float*       __restrict__ out)
{
    // Fused layout: slot i = { value bits (u32), inhibited flag (u32) }.
    // One LDS.64 gather returns both; marking is predicated on flag==0,
    // which kills ~88% of the STS traffic as the map saturates.
    extern __shared__ unsigned smem_u[];
    uint2* xs2 = (uint2*)smem_u;

    const int tid   = threadIdx.x;
    const int chunk = blockIdx.x;               // 0..15
    const int b     = blockIdx.y;               // 0..31

    // Prologue: load x row (coalesced), interleave with zero flags.
    const float* xrow = x + (size_t)b * NI;
    #pragma unroll
    for (int i = tid; i < NI; i += THREADS) {
        xs2[i] = make_uint2(__float_as_uint(xrow[i]), 0u);
    }
    __syncthreads();

    const int lane = tid & 31;
    const int warp = tid >> 5;
    const unsigned lt_mask = (1u << lane) - 1u;

    // Warp w owns DET_PER_WARP consecutive detectors; one detector row
    // == 128B == exactly one coalesced warp load.
    const int* dbase = det
        + ((size_t)(chunk * DET_PER_CTA + warp * DET_PER_WARP)) * KK + lane;

    #pragma unroll 4
    for (int i = 0; i < DET_PER_WARP; i++) {
        int id = __ldg(dbase + i * KK);
        uint2 p = xs2[id];                         // LDS.64: value + flag
        unsigned key = f32_order_key(p.x);
        unsigned mkey = __reduce_max_sync(0xffffffffu, key);
        bool eq = (key == mkey);
        unsigned bal = __ballot_sync(0xffffffffu, eq);
        // winner = lowest lane achieving max (matches jnp.argmax tie-break)
        bool winner = eq && ((bal & lt_mask) == 0u);
        // Mark loser only if not already marked (flag read came free).
        // Stale flag reads just cause a redundant benign write.
        if (!winner && p.y == 0u)
            smem_u[2 * id + 1] = 1u;
    }
    __syncthreads();

    // Flush: write 0.0 for every inhibited input of this batch row.
    // Union across the 16 chunk-CTAs of a batch is formed by all of them
    // writing 0 (init kernel already wrote 1.0 everywhere).
    float* orow = out + (size_t)b * NI;
    for (int i = tid; i < NI; i += THREADS)
        if (smem_u[2 * i + 1]) orow[i] = 0.0f;
}

extern "C" void kernel_launch(void* const* d_in, const int* in_sizes, int n_in,
                              void* d_out, int out_size) {
    const float* x   = (const float*)d_in[0];   // [32, 16384] f32
    const int*   det = (const int*)d_in[1];     // [65536, 32] i32
    float*       out = (float*)d_out;           // [32, 16384] f32

    (void)in_sizes; (void)n_in; (void)out_size;

    cudaFuncSetAttribute(inhibit_kernel,
                         cudaFuncAttributeMaxDynamicSharedMemorySize,
                         SMEM_BYTES);

    // Init output to 1.0 (spike unless inhibited).
    init_out_kernel<<<(BB * NI / 4) / 256, 256>>>((float4*)out);

    dim3 grid(NCHUNK, BB);
    inhibit_kernel<<<grid, THREADS, SMEM_BYTES>>>(x, det, out);
}